// round 4
// baseline (speedup 1.0000x reference)
#include <cuda_runtime.h>
#include <cuda_bf16.h>

// ---------------- scratch (device globals; zero-init at load, pads never written) ----
// g_tmp layout: [x:320][c:20][my:320][t:28]  (t 0..24 valid, 25..27 stay zero)
static __device__ float4 g_tmp4[28672000];          // 458.75 MB (float2 x 57,344,000)
// g_imt layout: [t:25][y:320][x:320]
static __device__ float2 g_imt[2560000];            // 20.5 MB
static __device__ float2 g_tw[320];                 // twiddle table (315 used)

// ---------------- complex helpers ----------------
__device__ __forceinline__ float2 cadd(float2 a, float2 b){ return make_float2(a.x+b.x, a.y+b.y); }
__device__ __forceinline__ float2 csub(float2 a, float2 b){ return make_float2(a.x-b.x, a.y-b.y); }
__device__ __forceinline__ float2 cmul(float2 a, float2 b){
    return make_float2(a.x*b.x - a.y*b.y, a.x*b.y + a.y*b.x);
}
__device__ __forceinline__ float2 cmuli(float2 a){ return make_float2(-a.y, a.x); }  // *(+i)

// inverse radix-5 butterfly: out[s] = sum_r v[r] * exp(+2*pi*i*r*s/5)
__device__ __forceinline__ void bfly5(float2 v[5]){
    const float C1 =  0.309016994374947424f, S1 = 0.951056516295153572f;
    const float C2 = -0.809016994374947424f, S2 = 0.587785252292473129f;
    const float2 w1 = make_float2(C1,  S1), w2 = make_float2(C2,  S2);
    const float2 w3 = make_float2(C2, -S2), w4 = make_float2(C1, -S1);
    float2 o0 = cadd(cadd(cadd(v[1], v[2]), cadd(v[3], v[4])), v[0]);
    float2 o1 = cadd(v[0], cadd(cadd(cmul(v[1],w1), cmul(v[2],w2)), cadd(cmul(v[3],w3), cmul(v[4],w4))));
    float2 o2 = cadd(v[0], cadd(cadd(cmul(v[1],w2), cmul(v[2],w4)), cadd(cmul(v[3],w1), cmul(v[4],w3))));
    float2 o3 = cadd(v[0], cadd(cadd(cmul(v[1],w3), cmul(v[2],w1)), cadd(cmul(v[3],w4), cmul(v[4],w2))));
    float2 o4 = cadd(v[0], cadd(cadd(cmul(v[1],w4), cmul(v[2],w3)), cadd(cmul(v[3],w2), cmul(v[4],w1))));
    v[0]=o0; v[1]=o1; v[2]=o2; v[3]=o3; v[4]=o4;
}

// Stockham radix-5 first stage (Ns=1, no twiddles). N=320 -> 64 work items / transform.
__device__ __forceinline__ void stage_r5(const float2* __restrict__ src, float2* __restrict__ dst,
                                         int nt, int stride, int tid, int nth){
    int total = nt * 64;
    for (int w = tid; w < total; w += nth){
        int tr = w >> 6, j = w & 63;
        const float2* s = src + tr * stride;
        float2*       d = dst + tr * stride;
        float2 v[5];
        #pragma unroll
        for (int r = 0; r < 5; r++) v[r] = s[j + 64*r];
        bfly5(v);
        #pragma unroll
        for (int r = 0; r < 5; r++) d[5*j + r] = v[r];
    }
}

// Stockham radix-4 inverse stage. N=320 -> 80 items / transform.
// tw[jm*3 + (r-1)] = exp(+2*pi*i * jm * r / (4*NS))
template<int NS>
__device__ __forceinline__ void stage_r4(const float2* __restrict__ src, float2* __restrict__ dst,
                                         const float2* __restrict__ tw,
                                         int nt, int stride, int tid, int nth){
    int total = nt * 80;
    for (int w = tid; w < total; w += nth){
        int tr = w / 80, j = w - tr*80;
        const float2* s = src + tr * stride;
        float2*       d = dst + tr * stride;
        int jm = j % NS;
        float2 v0 = s[j];
        float2 v1 = cmul(s[j +  80], tw[jm*3 + 0]);
        float2 v2 = cmul(s[j + 160], tw[jm*3 + 1]);
        float2 v3 = cmul(s[j + 240], tw[jm*3 + 2]);
        float2 t0 = cadd(v0, v2), t1 = csub(v0, v2);
        float2 t2 = cadd(v1, v3), t3 = cmuli(csub(v1, v3));
        int o = (j / NS) * (NS * 4) + jm;
        d[o]        = cadd(t0, t2);
        d[o + NS]   = cadd(t1, t3);
        d[o + 2*NS] = csub(t0, t2);
        d[o + 3*NS] = csub(t1, t3);
    }
}

// twiddles: [0,15) Ns=5 (denom 20), [15,75) Ns=20 (denom 80), [75,315) Ns=80 (denom 320)
__global__ void twinit_kernel(){
    int k = threadIdx.x;
    if (k >= 315) return;
    int q; float denom;
    if (k < 15)      { q = k;      denom = 20.f;  }
    else if (k < 75) { q = k - 15; denom = 80.f;  }
    else             { q = k - 75; denom = 320.f; }
    int jm = q / 3, r = q - jm*3 + 1;
    float ang = 6.28318530717958647692f * (float)(jm * r) / denom;
    float sn, cs; sincosf(ang, &sn, &cs);
    g_tw[k] = make_float2(cs, sn);   // e^{+i ang}: inverse transform
}

// ------------- Stage A: k*m*(-1)^(x+y), iFFT along y; block = (x, c, tgroup of 5 frames) -------
__global__ void __launch_bounds__(320) stageA_kernel(
    const float* __restrict__ kre, const float* __restrict__ kim,
    const float* __restrict__ mask){
    __shared__ float2 tw[315];
    __shared__ float2 bufA[5*321];
    __shared__ float2 bufB[5*321];
    const int x = blockIdx.x, c = blockIdx.y, tg = blockIdx.z;
    const int tid = threadIdx.x;
    for (int k = tid; k < 315; k += 320) tw[k] = g_tw[k];
    for (int w = tid; w < 320*5; w += 320){
        int y = w / 5, tt = w - y*5;
        int t = tg*5 + tt;
        int p = x*320 + y;
        float m  = mask[p*500 + c*25 + t];
        float kr = kre[p*20 + c];
        float ki = kim[p*20 + c];
        if ((x + y) & 1) m = -m;                 // fused pre-shift
        bufA[tt*321 + y] = make_float2(kr*m, ki*m);
    }
    __syncthreads();
    stage_r5    (bufA, bufB,        5, 321, tid, 320); __syncthreads();
    stage_r4<5> (bufB, bufA, tw,    5, 321, tid, 320); __syncthreads();
    stage_r4<20>(bufA, bufB, tw+15, 5, 321, tid, 320); __syncthreads();
    stage_r4<80>(bufB, bufA, tw+75, 5, 321, tid, 320); __syncthreads();
    float2* dst = ((float2*)g_tmp4) + (size_t)(x*20 + c) * (320*28);
    for (int w = tid; w < 320*5; w += 320){
        int my = w / 5, tt = w - my*5;
        dst[my*28 + tg*5 + tt] = bufA[tt*321 + my];
    }
}

// ------------- Stage B: iFFT along x, coil-combine conj(smaps); block = (my, t-quad) ----------
__global__ void __launch_bounds__(320) stageB_kernel(
    const float* __restrict__ sre, const float* __restrict__ sim){
    __shared__ float2 tw[315];
    __shared__ float2 bufA[4*320];
    __shared__ float2 bufB[4*320];
    const int my = blockIdx.x, tq = blockIdx.y;       // frames t = 4*tq + tt
    const int tid = threadIdx.x;                      // = x index
    for (int k = tid; k < 315; k += 320) tw[k] = g_tw[k];
    float2 acc[4];
    #pragma unroll
    for (int i = 0; i < 4; i++) acc[i] = make_float2(0.f, 0.f);
    for (int c = 0; c < 20; c++){
        __syncthreads();   // bufA reuse guard (and tw visibility on first iter)
        const float4* src = g_tmp4 + (size_t)((tid*20 + c)*320 + my)*14 + tq*2;
        float4 a = src[0], b = src[1];                // one aligned 32B sector: 4 frames
        bufA[       tid] = make_float2(a.x, a.y);
        bufA[ 320 + tid] = make_float2(a.z, a.w);
        bufA[ 640 + tid] = make_float2(b.x, b.y);
        bufA[ 960 + tid] = make_float2(b.z, b.w);
        __syncthreads();
        stage_r5    (bufA, bufB,        4, 320, tid, 320); __syncthreads();
        stage_r4<5> (bufB, bufA, tw,    4, 320, tid, 320); __syncthreads();
        stage_r4<20>(bufA, bufB, tw+15, 4, 320, tid, 320); __syncthreads();
        stage_r4<80>(bufB, bufA, tw+75, 4, 320, tid, 320); __syncthreads();
        int sp = (tid*320 + my)*20 + c;
        float2 S = make_float2(sre[sp], -sim[sp]);    // conj(smaps)
        #pragma unroll
        for (int tt = 0; tt < 4; tt++) acc[tt] = cadd(acc[tt], cmul(bufA[tt*320 + tid], S));
    }
    float sc = ((tid + my) & 1) ? -(1.f/320.f) : (1.f/320.f);   // post-shift + ortho norm
    #pragma unroll
    for (int tt = 0; tt < 4; tt++){
        int t = tq*4 + tt;
        if (t < 25)
            g_imt[((size_t)t*320 + my)*320 + tid] = make_float2(acc[tt].x*sc, acc[tt].y*sc);
    }
}

// ------------- Stage C: 25-frame bilinear warp + sum ------------------------------------------
__global__ void __launch_bounds__(256) stageC_kernel(
    const float* __restrict__ flow, float* __restrict__ out){
    int p = blockIdx.x*256 + threadIdx.x;             // 0..102399
    int x = p % 320;                                  // x fastest -> coalesced gathers
    int y = p / 320;
    const float* fl = flow + (x*320 + y)*50;          // [x][y][2][25]
    float2 acc = make_float2(0.f, 0.f);
    for (int t = 0; t < 25; t++){
        float u = fl[t], v = fl[25 + t];
        float xs = fminf(fmaxf((float)x + u, 0.f), 319.f);
        float ys = fminf(fmaxf((float)y + v, 0.f), 319.f);
        int x0 = (int)floorf(xs), y0 = (int)floorf(ys);
        int x1 = min(x0 + 1, 319), y1 = min(y0 + 1, 319);
        float wx = xs - (float)x0, wy = ys - (float)y0;
        const float2* im = g_imt + (size_t)t*102400;  // [y][x]
        float2 v00 = im[y0*320 + x0];
        float2 v10 = im[y0*320 + x1];
        float2 v01 = im[y1*320 + x0];
        float2 v11 = im[y1*320 + x1];
        float w00 = (1.f-wx)*(1.f-wy), w10 = wx*(1.f-wy);
        float w01 = (1.f-wx)*wy,       w11 = wx*wy;
        acc.x += v00.x*w00 + v10.x*w10 + v01.x*w01 + v11.x*w11;
        acc.y += v00.y*w00 + v10.y*w10 + v01.y*w01 + v11.y*w11;
    }
    out[x*320 + y]          = acc.x;                  // [2,Nx,Ny]: real plane
    out[102400 + x*320 + y] = acc.y;                  // imag plane
}

extern "C" void kernel_launch(void* const* d_in, const int* in_sizes, int n_in,
                              void* d_out, int out_size) {
    const float* kre  = (const float*)d_in[0];
    const float* kim  = (const float*)d_in[1];
    const float* mask = (const float*)d_in[2];
    const float* sre  = (const float*)d_in[3];
    const float* sim  = (const float*)d_in[4];
    const float* flow = (const float*)d_in[5];
    float* out = (float*)d_out;

    twinit_kernel<<<1, 320>>>();
    stageA_kernel<<<dim3(320, 20, 5), 320>>>(kre, kim, mask);
    stageB_kernel<<<dim3(320, 7), 320>>>(sre, sim);
    stageC_kernel<<<400, 256>>>(flow, out);
}

// round 7
// speedup vs baseline: 1.2780x; 1.2780x over previous
#include <cuda_runtime.h>
#include <cuda_bf16.h>

// ---------------- scratch (device globals; zero-init at load) ----------------
// g_tmp layout: [x:320][c:20][my:320][t:28]  (t 0..24 valid; 25..27 are FFTs of zero frames)
static __device__ float4 g_tmp4[28672000];          // 458.75 MB
// g_imt layout: [t:25][y:320][x:320]
static __device__ float2 g_imt[2560000];            // 20.5 MB
static __device__ float2 g_tw[320];                 // twiddle table (315 used)
static __device__ float2 g_kT[2048000];             // kspace transposed [c:20][x:320][y:320], sign-folded
static __device__ float2 g_sT[2048000];             // conj(smaps) transposed [my:320][c:20][x:320]

// ---------------- complex helpers ----------------
__device__ __forceinline__ float2 cadd(float2 a, float2 b){ return make_float2(a.x+b.x, a.y+b.y); }
__device__ __forceinline__ float2 csub(float2 a, float2 b){ return make_float2(a.x-b.x, a.y-b.y); }
__device__ __forceinline__ float2 cmul(float2 a, float2 b){
    return make_float2(a.x*b.x - a.y*b.y, a.x*b.y + a.y*b.x);
}
__device__ __forceinline__ float2 cmuli(float2 a){ return make_float2(-a.y, a.x); }  // *(+i)

// inverse radix-5 butterfly
__device__ __forceinline__ void bfly5(float2 v[5]){
    const float C1 =  0.309016994374947424f, S1 = 0.951056516295153572f;
    const float C2 = -0.809016994374947424f, S2 = 0.587785252292473129f;
    const float2 w1 = make_float2(C1,  S1), w2 = make_float2(C2,  S2);
    const float2 w3 = make_float2(C2, -S2), w4 = make_float2(C1, -S1);
    float2 o0 = cadd(cadd(cadd(v[1], v[2]), cadd(v[3], v[4])), v[0]);
    float2 o1 = cadd(v[0], cadd(cadd(cmul(v[1],w1), cmul(v[2],w2)), cadd(cmul(v[3],w3), cmul(v[4],w4))));
    float2 o2 = cadd(v[0], cadd(cadd(cmul(v[1],w2), cmul(v[2],w4)), cadd(cmul(v[3],w1), cmul(v[4],w3))));
    float2 o3 = cadd(v[0], cadd(cadd(cmul(v[1],w3), cmul(v[2],w1)), cadd(cmul(v[3],w4), cmul(v[4],w2))));
    float2 o4 = cadd(v[0], cadd(cadd(cmul(v[1],w4), cmul(v[2],w3)), cadd(cmul(v[3],w2), cmul(v[4],w1))));
    v[0]=o0; v[1]=o1; v[2]=o2; v[3]=o3; v[4]=o4;
}

// one radix-5 first-stage item (Ns=1): reads s[j+64r], writes d[5j+r]
__device__ __forceinline__ void r5_item(const float2* __restrict__ s, float2* __restrict__ d, int j){
    float2 v[5];
    #pragma unroll
    for (int r = 0; r < 5; r++) v[r] = s[j + 64*r];
    bfly5(v);
    #pragma unroll
    for (int r = 0; r < 5; r++) d[5*j + r] = v[r];
}

// one radix-4 inverse item: j = item idx, o = output base, twp = &tw[jm*3]
__device__ __forceinline__ void r4_item(const float2* __restrict__ s, float2* __restrict__ d,
                                        const float2* __restrict__ twp, int j, int o, int NS){
    float2 v0 = s[j];
    float2 v1 = cmul(s[j +  80], twp[0]);
    float2 v2 = cmul(s[j + 160], twp[1]);
    float2 v3 = cmul(s[j + 240], twp[2]);
    float2 t0 = cadd(v0, v2), t1 = csub(v0, v2);
    float2 t2 = cadd(v1, v3), t3 = cmuli(csub(v1, v3));
    d[o]        = cadd(t0, t2);
    d[o + NS]   = cadd(t1, t3);
    d[o + 2*NS] = csub(t0, t2);
    d[o + 3*NS] = csub(t1, t3);
}

// per-thread constant FFT indices for the nt=4, 320-thread mapping (stride 321)
struct FftIdx {
    int base;                 // tr*321
    int j;                    // item within transform (0..79)
    int o5, o20, o80;         // output offsets per stage
    int tp5, tp20, tp80;      // twiddle offsets (into tw[])
    int b5, j5;               // radix-5 stage (valid if tid<256): tr*321, tid&63
};
__device__ __forceinline__ FftIdx make_idx(int tid){
    FftIdx ix;
    int tr = tid / 80;
    int j  = tid - tr*80;
    ix.base = tr * 321;
    ix.j = j;
    int q5 = j / 5,  m5 = j - q5*5;
    int q20= j / 20, m20= j - q20*20;
    ix.o5  = q5*20 + m5;   ix.tp5  = m5*3;
    ix.o20 = q20*80 + m20; ix.tp20 = 15 + m20*3;
    ix.o80 = j;            ix.tp80 = 75 + j*3;
    ix.b5 = (tid >> 6) * 321;
    ix.j5 = tid & 63;
    return ix;
}

// run the 4-stage 320-pt inverse FFT on 4 transforms living in bufA (stride 321).
// Result ends in bufA. Caller must sync before first use of result.
__device__ __forceinline__ void fft320x4(float2* bufA, float2* bufB, const float2* tw,
                                         const FftIdx& ix, int tid){
    if (tid < 256) r5_item(bufA + ix.b5, bufB + ix.b5, ix.j5);
    __syncthreads();
    r4_item(bufB + ix.base, bufA + ix.base, tw + ix.tp5,  ix.j, ix.o5,  5);
    __syncthreads();
    r4_item(bufA + ix.base, bufB + ix.base, tw + ix.tp20, ix.j, ix.o20, 20);
    __syncthreads();
    r4_item(bufB + ix.base, bufA + ix.base, tw + ix.tp80, ix.j, ix.o80, 80);
    __syncthreads();
}

// twiddles: [0,15) Ns=5 (denom 20), [15,75) Ns=20 (denom 80), [75,315) Ns=80 (denom 320)
__global__ void twinit_kernel(){
    int k = threadIdx.x;
    if (k >= 315) return;
    int q; float denom;
    if (k < 15)      { q = k;      denom = 20.f;  }
    else if (k < 75) { q = k - 15; denom = 80.f;  }
    else             { q = k - 75; denom = 320.f; }
    int jm = q / 3, r = q - jm*3 + 1;
    float ang = 6.28318530717958647692f * (float)(jm * r) / denom;
    float sn, cs; sincosf(ang, &sn, &cs);
    g_tw[k] = make_float2(cs, sn);   // e^{+i ang}: inverse transform
}

// ------------- prep: transpose kspace (sign-folded) and conj(smaps) ---------------------------
__global__ void __launch_bounds__(256) prep_kernel(
    const float* __restrict__ kre, const float* __restrict__ kim,
    const float* __restrict__ sre, const float* __restrict__ sim){
    int p = blockIdx.x*256 + threadIdx.x;             // 0..102399
    // kspace: p = x*320+y (input-major), write g_kT[c][x][y]
    {
        int x = p / 320, y = p - x*320;
        float sg = ((x + y) & 1) ? -1.f : 1.f;
        #pragma unroll 4
        for (int c = 0; c < 20; c++){
            float2 v = make_float2(kre[p*20 + c]*sg, kim[p*20 + c]*sg);
            g_kT[c*102400 + p] = v;
        }
    }
    // smaps: thread p = my*320+x (output-major); read s[(x*320+my)*20+c]
    {
        int my = p / 320, x = p - my*320;
        int src = (x*320 + my)*20;
        #pragma unroll 4
        for (int c = 0; c < 20; c++){
            g_sT[(my*20 + c)*320 + x] = make_float2(sre[src + c], -sim[src + c]);  // conj folded
        }
    }
}

// ------------- Stage A: mask*kT, iFFT along y; block = (x, c, t-quad incl. 3 zero pad frames) -
__global__ void __launch_bounds__(320) stageA_kernel(const float* __restrict__ mask){
    __shared__ float2 tw[315];
    __shared__ float2 bufA[4*321];
    __shared__ float2 bufB[4*321];
    const int x = blockIdx.x, c = blockIdx.y, tq = blockIdx.z;   // t = 4*tq + tt
    const int tid = threadIdx.x;                                  // = y index
    if (tid < 315) tw[tid] = g_tw[tid];
    const FftIdx ix = make_idx(tid);

    // load: one (x,c) k-value (broadcast), 4 mask values (t quad, 16B run)
    float2 kv = g_kT[c*102400 + x*320 + tid];
    const float* mrow = mask + (x*320 + tid)*500 + c*25 + tq*4;
    #pragma unroll
    for (int tt = 0; tt < 4; tt++){
        int t = tq*4 + tt;
        float m = (t < 25) ? mrow[tt] : 0.f;
        bufA[tt*321 + tid] = make_float2(kv.x*m, kv.y*m);
    }
    __syncthreads();

    fft320x4(bufA, bufB, tw, ix, tid);

    // store: each thread owns one my row -> 32B aligned, 2x STG.128
    float2 r0 = bufA[        tid];
    float2 r1 = bufA[ 321 + tid];
    float2 r2 = bufA[ 642 + tid];
    float2 r3 = bufA[ 963 + tid];
    float4* d4 = (float4*)(((float2*)g_tmp4) + (size_t)(x*20 + c)*8960 + tid*28 + tq*4);
    d4[0] = make_float4(r0.x, r0.y, r1.x, r1.y);
    d4[1] = make_float4(r2.x, r2.y, r3.x, r3.y);
}

// ------------- Stage B: iFFT along x, coil-combine conj(smaps); block = (my, t-quad) ----------
__global__ void __launch_bounds__(320) stageB_kernel(){
    __shared__ float2 tw[315];
    __shared__ float2 bufA[4*321];
    __shared__ float2 bufB[4*321];
    const int my = blockIdx.x, tq = blockIdx.y;       // frames t = 4*tq + tt
    const int tid = threadIdx.x;                      // = x index
    if (tid < 315) tw[tid] = g_tw[tid];
    const FftIdx ix = make_idx(tid);

    float2 acc[4];
    #pragma unroll
    for (int i = 0; i < 4; i++) acc[i] = make_float2(0.f, 0.f);

    // prefetch coil 0
    const float4* sp = g_tmp4 + (size_t)((tid*20 + 0)*320 + my)*14 + tq*2;
    float4 pa = sp[0], pb = sp[1];

    for (int c = 0; c < 20; c++){
        __syncthreads();                               // bufA free (prev acc read done); tw ready (c=0)
        bufA[       tid] = make_float2(pa.x, pa.y);
        bufA[ 321 + tid] = make_float2(pa.z, pa.w);
        bufA[ 642 + tid] = make_float2(pb.x, pb.y);
        bufA[ 963 + tid] = make_float2(pb.z, pb.w);
        __syncthreads();

        if (tid < 256) r5_item(bufA + ix.b5, bufB + ix.b5, ix.j5);
        __syncthreads();
        if (c < 19){                                   // prefetch next coil under FFT stages
            const float4* spn = g_tmp4 + (size_t)((tid*20 + c + 1)*320 + my)*14 + tq*2;
            pa = spn[0]; pb = spn[1];
        }
        r4_item(bufB + ix.base, bufA + ix.base, tw + ix.tp5,  ix.j, ix.o5,  5);
        __syncthreads();
        r4_item(bufA + ix.base, bufB + ix.base, tw + ix.tp20, ix.j, ix.o20, 20);
        __syncthreads();
        r4_item(bufB + ix.base, bufA + ix.base, tw + ix.tp80, ix.j, ix.o80, 80);
        __syncthreads();

        float2 S = g_sT[(my*20 + c)*320 + tid];        // conj(smaps), coalesced
        #pragma unroll
        for (int tt = 0; tt < 4; tt++) acc[tt] = cadd(acc[tt], cmul(bufA[tt*321 + tid], S));
    }

    float sc = ((tid + my) & 1) ? -(1.f/320.f) : (1.f/320.f);   // post-shift + ortho norm
    #pragma unroll
    for (int tt = 0; tt < 4; tt++){
        int t = tq*4 + tt;
        if (t < 25)
            g_imt[((size_t)t*320 + my)*320 + tid] = make_float2(acc[tt].x*sc, acc[tt].y*sc);
    }
}

// ------------- Stage C: 25-frame bilinear warp + sum ------------------------------------------
__global__ void __launch_bounds__(256) stageC_kernel(
    const float* __restrict__ flow, float* __restrict__ out){
    int p = blockIdx.x*256 + threadIdx.x;             // 0..102399
    int x = p % 320;                                  // x fastest -> coalesced gathers
    int y = p / 320;
    const float* fl = flow + (x*320 + y)*50;          // [x][y][2][25]
    float2 acc = make_float2(0.f, 0.f);
    for (int t = 0; t < 25; t++){
        float u = fl[t], v = fl[25 + t];
        float xs = fminf(fmaxf((float)x + u, 0.f), 319.f);
        float ys = fminf(fmaxf((float)y + v, 0.f), 319.f);
        int x0 = (int)floorf(xs), y0 = (int)floorf(ys);
        int x1 = min(x0 + 1, 319), y1 = min(y0 + 1, 319);
        float wx = xs - (float)x0, wy = ys - (float)y0;
        const float2* im = g_imt + (size_t)t*102400;  // [y][x]
        float2 v00 = im[y0*320 + x0];
        float2 v10 = im[y0*320 + x1];
        float2 v01 = im[y1*320 + x0];
        float2 v11 = im[y1*320 + x1];
        float w00 = (1.f-wx)*(1.f-wy), w10 = wx*(1.f-wy);
        float w01 = (1.f-wx)*wy,       w11 = wx*wy;
        acc.x += v00.x*w00 + v10.x*w10 + v01.x*w01 + v11.x*w11;
        acc.y += v00.y*w00 + v10.y*w10 + v01.y*w01 + v11.y*w11;
    }
    out[x*320 + y]          = acc.x;                  // [2,Nx,Ny]: real plane
    out[102400 + x*320 + y] = acc.y;                  // imag plane
}

extern "C" void kernel_launch(void* const* d_in, const int* in_sizes, int n_in,
                              void* d_out, int out_size) {
    const float* kre  = (const float*)d_in[0];
    const float* kim  = (const float*)d_in[1];
    const float* mask = (const float*)d_in[2];
    const float* sre  = (const float*)d_in[3];
    const float* sim  = (const float*)d_in[4];
    const float* flow = (const float*)d_in[5];
    float* out = (float*)d_out;

    twinit_kernel<<<1, 320>>>();
    prep_kernel<<<400, 256>>>(kre, kim, sre, sim);
    stageA_kernel<<<dim3(320, 20, 7), 320>>>(mask);
    stageB_kernel<<<dim3(320, 7), 320>>>();
    stageC_kernel<<<400, 256>>>(flow, out);
}

// round 8
// speedup vs baseline: 1.6679x; 1.3052x over previous
#include <cuda_runtime.h>
#include <cuda_fp16.h>

// ---------------- scratch (device globals; zero-init at load) ----------------
// g_tmpH layout: [x:320][c:20][my:320][t:32] as half2  (t 0..24 valid; 25..31 zero)
static __device__ uint4 g_tmpH[16384000];           // 262.1 MB
// g_imt layout: [t:25][y:320][x:320]
static __device__ float2 g_imt[2560000];            // 20.5 MB
static __device__ float2 g_tw[320];                 // twiddle table (315 used)
static __device__ float2 g_kT[2048000];             // kspace transposed [c:20][x:320][y:320], sign-folded
static __device__ float2 g_sT[2048000];             // conj(smaps) transposed [my:320][c:20][x:320]

// ---------------- complex helpers ----------------
__device__ __forceinline__ float2 cadd(float2 a, float2 b){ return make_float2(a.x+b.x, a.y+b.y); }
__device__ __forceinline__ float2 csub(float2 a, float2 b){ return make_float2(a.x-b.x, a.y-b.y); }
__device__ __forceinline__ float2 cmul(float2 a, float2 b){
    return make_float2(a.x*b.x - a.y*b.y, a.x*b.y + a.y*b.x);
}
__device__ __forceinline__ float2 cmuli(float2 a){ return make_float2(-a.y, a.x); }  // *(+i)

// inverse radix-5 butterfly
__device__ __forceinline__ void bfly5(float2 v[5]){
    const float C1 =  0.309016994374947424f, S1 = 0.951056516295153572f;
    const float C2 = -0.809016994374947424f, S2 = 0.587785252292473129f;
    const float2 w1 = make_float2(C1,  S1), w2 = make_float2(C2,  S2);
    const float2 w3 = make_float2(C2, -S2), w4 = make_float2(C1, -S1);
    float2 o0 = cadd(cadd(cadd(v[1], v[2]), cadd(v[3], v[4])), v[0]);
    float2 o1 = cadd(v[0], cadd(cadd(cmul(v[1],w1), cmul(v[2],w2)), cadd(cmul(v[3],w3), cmul(v[4],w4))));
    float2 o2 = cadd(v[0], cadd(cadd(cmul(v[1],w2), cmul(v[2],w4)), cadd(cmul(v[3],w1), cmul(v[4],w3))));
    float2 o3 = cadd(v[0], cadd(cadd(cmul(v[1],w3), cmul(v[2],w1)), cadd(cmul(v[3],w4), cmul(v[4],w2))));
    float2 o4 = cadd(v[0], cadd(cadd(cmul(v[1],w4), cmul(v[2],w3)), cadd(cmul(v[3],w2), cmul(v[4],w1))));
    v[0]=o0; v[1]=o1; v[2]=o2; v[3]=o3; v[4]=o4;
}

// one radix-5 first-stage item (Ns=1): reads s[j+64r], writes d[5j+r]
__device__ __forceinline__ void r5_item(const float2* __restrict__ s, float2* __restrict__ d, int j){
    float2 v[5];
    #pragma unroll
    for (int r = 0; r < 5; r++) v[r] = s[j + 64*r];
    bfly5(v);
    #pragma unroll
    for (int r = 0; r < 5; r++) d[5*j + r] = v[r];
}

// one radix-4 inverse item
__device__ __forceinline__ void r4_item(const float2* __restrict__ s, float2* __restrict__ d,
                                        const float2* __restrict__ twp, int j, int o, int NS){
    float2 v0 = s[j];
    float2 v1 = cmul(s[j +  80], twp[0]);
    float2 v2 = cmul(s[j + 160], twp[1]);
    float2 v3 = cmul(s[j + 240], twp[2]);
    float2 t0 = cadd(v0, v2), t1 = csub(v0, v2);
    float2 t2 = cadd(v1, v3), t3 = cmuli(csub(v1, v3));
    d[o]        = cadd(t0, t2);
    d[o + NS]   = cadd(t1, t3);
    d[o + 2*NS] = csub(t0, t2);
    d[o + 3*NS] = csub(t1, t3);
}

// per-thread constant FFT indices for the nt=4, 320-thread mapping (stride 321)
struct FftIdx {
    int base, j;
    int o5, o20, o80;
    int tp5, tp20, tp80;
    int b5, j5;
};
__device__ __forceinline__ FftIdx make_idx(int tid){
    FftIdx ix;
    int tr = tid / 80;
    int j  = tid - tr*80;
    ix.base = tr * 321;
    ix.j = j;
    int q5 = j / 5,  m5 = j - q5*5;
    int q20= j / 20, m20= j - q20*20;
    ix.o5  = q5*20 + m5;   ix.tp5  = m5*3;
    ix.o20 = q20*80 + m20; ix.tp20 = 15 + m20*3;
    ix.o80 = j;            ix.tp80 = 75 + j*3;
    ix.b5 = (tid >> 6) * 321;
    ix.j5 = tid & 63;
    return ix;
}

// 4-stage 320-pt inverse FFT on 4 transforms in bufA (stride 321). Result in bufA.
__device__ __forceinline__ void fft320x4(float2* bufA, float2* bufB, const float2* tw,
                                         const FftIdx& ix, int tid){
    if (tid < 256) r5_item(bufA + ix.b5, bufB + ix.b5, ix.j5);
    __syncthreads();
    r4_item(bufB + ix.base, bufA + ix.base, tw + ix.tp5,  ix.j, ix.o5,  5);
    __syncthreads();
    r4_item(bufA + ix.base, bufB + ix.base, tw + ix.tp20, ix.j, ix.o20, 20);
    __syncthreads();
    r4_item(bufB + ix.base, bufA + ix.base, tw + ix.tp80, ix.j, ix.o80, 80);
    __syncthreads();
}

// twiddles: [0,15) Ns=5 (denom 20), [15,75) Ns=20 (denom 80), [75,315) Ns=80 (denom 320)
__global__ void twinit_kernel(){
    int k = threadIdx.x;
    if (k >= 315) return;
    int q; float denom;
    if (k < 15)      { q = k;      denom = 20.f;  }
    else if (k < 75) { q = k - 15; denom = 80.f;  }
    else             { q = k - 75; denom = 320.f; }
    int jm = q / 3, r = q - jm*3 + 1;
    float ang = 6.28318530717958647692f * (float)(jm * r) / denom;
    float sn, cs; sincosf(ang, &sn, &cs);
    g_tw[k] = make_float2(cs, sn);   // e^{+i ang}: inverse transform
}

// ------------- prep: transpose kspace (sign-folded) and conj(smaps) ---------------------------
__global__ void __launch_bounds__(256) prep_kernel(
    const float* __restrict__ kre, const float* __restrict__ kim,
    const float* __restrict__ sre, const float* __restrict__ sim){
    int p = blockIdx.x*256 + threadIdx.x;             // 0..102399
    {
        int x = p / 320, y = p - x*320;
        float sg = ((x + y) & 1) ? -1.f : 1.f;
        #pragma unroll 4
        for (int c = 0; c < 20; c++){
            g_kT[c*102400 + p] = make_float2(kre[p*20 + c]*sg, kim[p*20 + c]*sg);
        }
    }
    {
        int my = p / 320, x = p - my*320;
        int src = (x*320 + my)*20;
        #pragma unroll 4
        for (int c = 0; c < 20; c++){
            g_sT[(my*20 + c)*320 + x] = make_float2(sre[src + c], -sim[src + c]);  // conj folded
        }
    }
}

// ------------- Stage A: mask*kT, iFFT along y; block = (x, c, t-half of 16) -------------------
// half 0: quads t0-15 (4 FFT quads). half 1: quads t16-27 (3 FFT quads) + t28-31 zeros.
__global__ void __launch_bounds__(320, 2) stageA_kernel(const float* __restrict__ mask){
    __shared__ float2 tw[315];
    __shared__ float2 bufA[4*321];
    __shared__ float2 bufB[4*321];
    const int x = blockIdx.x, c = blockIdx.y, half = blockIdx.z;
    const int tid = threadIdx.x;                                  // = y index
    if (tid < 315) tw[tid] = g_tw[tid];
    const FftIdx ix = make_idx(tid);

    const float2 kv = g_kT[c*102400 + x*320 + tid];
    const float* mrow = mask + (x*320 + tid)*500 + c*25;
    const int nq = half ? 3 : 4;
    unsigned int outv[16];

    #pragma unroll
    for (int q = 0; q < 4; q++){
        if (q < nq){
            const int t0 = half*16 + q*4;
            __syncthreads();                           // bufA free from prev quad's result reads
            #pragma unroll
            for (int tt = 0; tt < 4; tt++){
                int t = t0 + tt;
                float m = (t < 25) ? mrow[t] : 0.f;
                bufA[tt*321 + tid] = make_float2(kv.x*m, kv.y*m);
            }
            __syncthreads();
            fft320x4(bufA, bufB, tw, ix, tid);
            #pragma unroll
            for (int tt = 0; tt < 4; tt++){
                float2 r = bufA[tt*321 + tid];         // thread owns my = tid
                __half2 h = __floats2half2_rn(r.x, r.y);
                outv[q*4 + tt] = *reinterpret_cast<unsigned int*>(&h);
            }
        } else {
            #pragma unroll
            for (int tt = 0; tt < 4; tt++) outv[q*4 + tt] = 0u;   // t28-31 zero frames
        }
    }
    // 64B contiguous store per thread
    uint4* dst = g_tmpH + ((size_t)(x*20 + c)*320 + tid)*8 + half*4;
    #pragma unroll
    for (int i = 0; i < 4; i++)
        dst[i] = make_uint4(outv[4*i], outv[4*i+1], outv[4*i+2], outv[4*i+3]);
}

// ------------- Stage B: iFFT along x, coil-combine conj(smaps); block = (my, t-half) ----------
__global__ void __launch_bounds__(320, 2) stageB_kernel(){
    __shared__ float2 tw[315];
    __shared__ float2 bufA[4*321];
    __shared__ float2 bufB[4*321];
    const int my = blockIdx.x, half = blockIdx.y;
    const int tid = threadIdx.x;                      // = x index
    if (tid < 315) tw[tid] = g_tw[tid];
    const FftIdx ix = make_idx(tid);
    const int nq = half ? 3 : 4;

    float2 acc[16];
    #pragma unroll
    for (int i = 0; i < 16; i++) acc[i] = make_float2(0.f, 0.f);

    // prefetch coil 0 (64B contiguous per thread)
    uint4 pf[4];
    {
        const uint4* s0 = g_tmpH + ((size_t)(tid*20 + 0)*320 + my)*8 + half*4;
        #pragma unroll
        for (int i = 0; i < 4; i++) if (i < nq) pf[i] = s0[i];
    }

    for (int c = 0; c < 20; c++){
        uint4 cur[4];
        #pragma unroll
        for (int i = 0; i < 4; i++) if (i < nq) cur[i] = pf[i];
        if (c < 19){
            const uint4* sn = g_tmpH + ((size_t)(tid*20 + c + 1)*320 + my)*8 + half*4;
            #pragma unroll
            for (int i = 0; i < 4; i++) if (i < nq) pf[i] = sn[i];
        }
        const float2 S = g_sT[(my*20 + c)*320 + tid];  // conj(smaps), coalesced

        #pragma unroll
        for (int q = 0; q < 4; q++){
            if (q >= nq) continue;
            __syncthreads();                           // bufA free (prev acc reads done); tw ready (c=0,q=0)
            unsigned int v0 = cur[q].x, v1 = cur[q].y, v2 = cur[q].z, v3 = cur[q].w;
            bufA[        tid] = __half22float2(*reinterpret_cast<__half2*>(&v0));
            bufA[ 321 + tid] = __half22float2(*reinterpret_cast<__half2*>(&v1));
            bufA[ 642 + tid] = __half22float2(*reinterpret_cast<__half2*>(&v2));
            bufA[ 963 + tid] = __half22float2(*reinterpret_cast<__half2*>(&v3));
            __syncthreads();
            fft320x4(bufA, bufB, tw, ix, tid);
            #pragma unroll
            for (int tt = 0; tt < 4; tt++)
                acc[q*4 + tt] = cadd(acc[q*4 + tt], cmul(bufA[tt*321 + tid], S));
        }
    }

    const float sc = ((tid + my) & 1) ? -(1.f/320.f) : (1.f/320.f);   // post-shift + ortho norm
    #pragma unroll
    for (int i = 0; i < 16; i++){
        int t = half*16 + i;
        if (i < nq*4 && t < 25)
            g_imt[((size_t)t*320 + my)*320 + tid] = make_float2(acc[i].x*sc, acc[i].y*sc);
    }
}

// ------------- Stage C: 25-frame bilinear warp + sum ------------------------------------------
__global__ void __launch_bounds__(256) stageC_kernel(
    const float* __restrict__ flow, float* __restrict__ out){
    int p = blockIdx.x*256 + threadIdx.x;             // 0..102399
    int x = p % 320;                                  // x fastest -> coalesced gathers
    int y = p / 320;
    const float* fl = flow + (x*320 + y)*50;          // [x][y][2][25]
    float2 acc = make_float2(0.f, 0.f);
    for (int t = 0; t < 25; t++){
        float u = fl[t], v = fl[25 + t];
        float xs = fminf(fmaxf((float)x + u, 0.f), 319.f);
        float ys = fminf(fmaxf((float)y + v, 0.f), 319.f);
        int x0 = (int)floorf(xs), y0 = (int)floorf(ys);
        int x1 = min(x0 + 1, 319), y1 = min(y0 + 1, 319);
        float wx = xs - (float)x0, wy = ys - (float)y0;
        const float2* im = g_imt + (size_t)t*102400;  // [y][x]
        float2 v00 = im[y0*320 + x0];
        float2 v10 = im[y0*320 + x1];
        float2 v01 = im[y1*320 + x0];
        float2 v11 = im[y1*320 + x1];
        float w00 = (1.f-wx)*(1.f-wy), w10 = wx*(1.f-wy);
        float w01 = (1.f-wx)*wy,       w11 = wx*wy;
        acc.x += v00.x*w00 + v10.x*w10 + v01.x*w01 + v11.x*w11;
        acc.y += v00.y*w00 + v10.y*w10 + v01.y*w01 + v11.y*w11;
    }
    out[x*320 + y]          = acc.x;                  // [2,Nx,Ny]: real plane
    out[102400 + x*320 + y] = acc.y;                  // imag plane
}

extern "C" void kernel_launch(void* const* d_in, const int* in_sizes, int n_in,
                              void* d_out, int out_size) {
    const float* kre  = (const float*)d_in[0];
    const float* kim  = (const float*)d_in[1];
    const float* mask = (const float*)d_in[2];
    const float* sre  = (const float*)d_in[3];
    const float* sim  = (const float*)d_in[4];
    const float* flow = (const float*)d_in[5];
    float* out = (float*)d_out;

    twinit_kernel<<<1, 320>>>();
    prep_kernel<<<400, 256>>>(kre, kim, sre, sim);
    stageA_kernel<<<dim3(320, 20, 2), 320>>>(mask);
    stageB_kernel<<<dim3(320, 2), 320>>>();
    stageC_kernel<<<400, 256>>>(flow, out);
}

// round 12
// speedup vs baseline: 1.7271x; 1.0355x over previous
#include <cuda_runtime.h>
#include <cuda_fp16.h>

// ---------------- scratch (device globals; zero-init at load) ----------------
// g_tmpH layout: [x:320][c:20][my:320][t:32] as half2  (t 0..24 valid; 25..31 zero)
static __device__ uint4 g_tmpH[16384000];           // 262.1 MB
// g_imt layout: [t:25][y:320][x:320]
static __device__ float2 g_imt[2560000];            // 20.5 MB
static __device__ float2 g_tw320[320];              // e^{+2pi i j/320}
static __device__ float2 g_kT[2048000];             // kspace transposed [c:20][x:320][y:320], sign-folded
static __device__ float2 g_sT[2048000];             // conj(smaps) transposed [my:320][c:20][x:320]

// ---------------- complex helpers ----------------
__device__ __forceinline__ float2 cadd(float2 a, float2 b){ return make_float2(a.x+b.x, a.y+b.y); }
__device__ __forceinline__ float2 csub(float2 a, float2 b){ return make_float2(a.x-b.x, a.y-b.y); }
__device__ __forceinline__ float2 cmul(float2 a, float2 b){
    return make_float2(a.x*b.x - a.y*b.y, a.x*b.y + a.y*b.x);
}
__device__ __forceinline__ float2 cmuli(float2 a){ return make_float2(-a.y, a.x); }  // *(+i)

// inverse 4-pt DFT: X_s = sum_r v_r e^{+2pi i rs/4}
__device__ __forceinline__ void dft4(float2 a, float2 b, float2 c, float2 d,
                                     float2& X0, float2& X1, float2& X2, float2& X3){
    float2 ac = cadd(a,c), amc = csub(a,c);
    float2 bd = cadd(b,d), bmd = csub(b,d);
    float2 ibmd = cmuli(bmd);
    X0 = cadd(ac, bd);
    X1 = cadd(amc, ibmd);
    X2 = csub(ac, bd);
    X3 = csub(amc, ibmd);
}

// inverse radix-5 butterfly: out[s] = sum_r v[r] e^{+2pi i rs/5}
__device__ __forceinline__ void bfly5(float2 v[5]){
    const float C1 =  0.309016994374947424f, S1 = 0.951056516295153572f;
    const float C2 = -0.809016994374947424f, S2 = 0.587785252292473129f;
    const float2 w1 = make_float2(C1,  S1), w2 = make_float2(C2,  S2);
    const float2 w3 = make_float2(C2, -S2), w4 = make_float2(C1, -S1);
    float2 o0 = cadd(cadd(cadd(v[1], v[2]), cadd(v[3], v[4])), v[0]);
    float2 o1 = cadd(v[0], cadd(cadd(cmul(v[1],w1), cmul(v[2],w2)), cadd(cmul(v[3],w3), cmul(v[4],w4))));
    float2 o2 = cadd(v[0], cadd(cadd(cmul(v[1],w2), cmul(v[2],w4)), cadd(cmul(v[3],w1), cmul(v[4],w3))));
    float2 o3 = cadd(v[0], cadd(cadd(cmul(v[1],w3), cmul(v[2],w1)), cadd(cmul(v[3],w4), cmul(v[4],w2))));
    float2 o4 = cadd(v[0], cadd(cadd(cmul(v[1],w4), cmul(v[2],w3)), cadd(cmul(v[3],w2), cmul(v[4],w1))));
    v[0]=o0; v[1]=o1; v[2]=o2; v[3]=o3; v[4]=o4;
}

// inverse 16-pt FFT, natural order in/out (16 = 4x4 Cooley-Tukey, e^{+i})
__device__ __forceinline__ void fft16_reg(float2 v[16]){
    const float2 W[10] = {   // e^{+2pi i k/16}, k=0..9
      { 1.f, 0.f},
      { 0.92387953251128675613f, 0.38268343236508977173f},
      { 0.70710678118654752440f, 0.70710678118654752440f},
      { 0.38268343236508977173f, 0.92387953251128675613f},
      { 0.f, 1.f},
      {-0.38268343236508977173f, 0.92387953251128675613f},
      {-0.70710678118654752440f, 0.70710678118654752440f},
      {-0.92387953251128675613f, 0.38268343236508977173f},
      {-1.f, 0.f},
      {-0.92387953251128675613f,-0.38268343236508977173f},
    };
    float2 A[16];            // A[n1*4 + m]
    #pragma unroll
    for (int n1 = 0; n1 < 4; n1++)
        dft4(v[n1], v[n1+4], v[n1+8], v[n1+12],
             A[n1*4+0], A[n1*4+1], A[n1*4+2], A[n1*4+3]);
    #pragma unroll
    for (int m = 0; m < 4; m++){
        float2 b0 = A[m];
        float2 b1 = cmul(A[4+m],  W[m]);
        float2 b2 = cmul(A[8+m],  W[2*m]);
        float2 b3 = cmul(A[12+m], W[3*m]);
        dft4(b0,b1,b2,b3, v[m], v[m+4], v[m+8], v[m+12]);   // out[m+4p]
    }
}

// inverse 20-pt DFT, natural order in/out (20 = 4x5 Cooley-Tukey, e^{+i})
__device__ __forceinline__ void dft20_reg(float2 v[20]){
    const float2 W[13] = {   // e^{+2pi i k/20}, k=0..12
      { 1.f, 0.f},
      { 0.95105651629515357212f, 0.30901699437494742410f},
      { 0.80901699437494742410f, 0.58778525229247312917f},
      { 0.58778525229247312917f, 0.80901699437494742410f},
      { 0.30901699437494742410f, 0.95105651629515357212f},
      { 0.f, 1.f},
      {-0.30901699437494742410f, 0.95105651629515357212f},
      {-0.58778525229247312917f, 0.80901699437494742410f},
      {-0.80901699437494742410f, 0.58778525229247312917f},
      {-0.95105651629515357212f, 0.30901699437494742410f},
      {-1.f, 0.f},
      {-0.95105651629515357212f,-0.30901699437494742410f},
      {-0.80901699437494742410f,-0.58778525229247312917f},
    };
    float2 A[20];            // A[a*5 + m]
    #pragma unroll
    for (int a = 0; a < 4; a++){
        float2 t[5];
        #pragma unroll
        for (int b = 0; b < 5; b++) t[b] = v[a + 4*b];
        bfly5(t);
        #pragma unroll
        for (int m = 0; m < 5; m++) A[a*5+m] = t[m];
    }
    #pragma unroll
    for (int m = 0; m < 5; m++){
        float2 b0 = A[m];
        float2 b1 = cmul(A[5+m],  W[m]);
        float2 b2 = cmul(A[10+m], W[2*m]);
        float2 b3 = cmul(A[15+m], W[3*m]);
        dft4(b0,b1,b2,b3, v[m], v[m+5], v[m+10], v[m+15]);  // out[m+5q]
    }
}

__global__ void twinit_kernel(){
    int j = threadIdx.x;
    float ang = 6.28318530717958647692f * (float)j / 320.f;
    float sn, cs; sincosf(ang, &sn, &cs);
    g_tw320[j] = make_float2(cs, sn);   // e^{+i ang}
}

// ------------- prep: transpose kspace (sign-folded) and conj(smaps) ---------------------------
__global__ void __launch_bounds__(256) prep_kernel(
    const float* __restrict__ kre, const float* __restrict__ kim,
    const float* __restrict__ sre, const float* __restrict__ sim){
    int p = blockIdx.x*256 + threadIdx.x;             // 0..102399
    {
        int x = p / 320, y = p - x*320;
        float sg = ((x + y) & 1) ? -1.f : 1.f;
        #pragma unroll 4
        for (int c = 0; c < 20; c++){
            g_kT[c*102400 + p] = make_float2(kre[p*20 + c]*sg, kim[p*20 + c]*sg);
        }
    }
    {
        int my = p / 320, x = p - my*320;
        int src = (x*320 + my)*20;
        #pragma unroll 4
        for (int c = 0; c < 20; c++){
            g_sT[(my*20 + c)*320 + x] = make_float2(sre[src + c], -sim[src + c]);  // conj folded
        }
    }
}

// ------------- Stage A: mask*kT, iFFT along y (four-step 20x16); block = (x, c, t-half) -------
// dynamic smem: sIn[16*321] | sMid[16*336] | tw[320]   = 86656 B
__global__ void __launch_bounds__(320, 2) stageA_kernel(const float* __restrict__ mask){
    extern __shared__ float2 dyn[];
    float2* sIn  = dyn;                 // [f][y]  stride 321
    float2* sMid = sIn + 16*321;        // [f][m2*21 + n1]  (n1: 0..19, pad to 21)
    float2* tw   = sMid + 16*336;       // 320 entries
    const int x = blockIdx.x, c = blockIdx.y, half = blockIdx.z;
    const int tid = threadIdx.x;        // = y
    tw[tid] = g_tw320[tid];

    const float2 kv = g_kT[c*102400 + x*320 + tid];
    const float* mrow = mask + (x*320 + tid)*500 + c*25 + half*16;
    const int nv = half ? 9 : 16;       // valid frames in this half
    #pragma unroll
    for (int f = 0; f < 16; f++){
        float m = (f < nv) ? mrow[f] : 0.f;
        sIn[f*321 + tid] = make_float2(kv.x*m, kv.y*m);
    }
    __syncthreads();

    // phase 1: (f, n1), n1 in 0..19 — 320 tasks; 16-pt FFT over n2 (stride 20)
    {
        const int f = tid / 20, n1 = tid % 20;
        const float2* base = sIn + f*321;
        float2 v[16];
        #pragma unroll
        for (int n2 = 0; n2 < 16; n2++) v[n2] = base[n1 + 20*n2];
        fft16_reg(v);
        float2* mb = sMid + f*336 + n1;
        int idx = 0;                                  // n1*m2 mod 320
        #pragma unroll
        for (int m2 = 0; m2 < 16; m2++){
            mb[m2*21] = cmul(v[m2], tw[idx]);
            idx += n1; if (idx >= 320) idx -= 320;
        }
    }
    __syncthreads();

    // phase 2: (f, m2) — 256 tasks; 20-pt DFT over n1; out[p] = X[m2+16p]
    if (tid < 256){
        const int f = tid >> 4, m2 = tid & 15;
        const float2* mb = sMid + f*336 + m2*21;
        float2 v[20];
        #pragma unroll
        for (int n1 = 0; n1 < 20; n1++) v[n1] = mb[n1];
        dft20_reg(v);
        float2* ob = sIn + f*321 + m2;
        #pragma unroll
        for (int p = 0; p < 20; p++) ob[16*p] = v[p];   // my = m2 + 16p
    }
    __syncthreads();

    // store: thread = my, 16 frames -> 64B contiguous fp16
    uint4* dst = g_tmpH + ((size_t)(x*20 + c)*320 + tid)*8 + half*4;
    #pragma unroll
    for (int i = 0; i < 4; i++){
        unsigned int u[4];
        #pragma unroll
        for (int j = 0; j < 4; j++){
            float2 r = sIn[(4*i+j)*321 + tid];
            __half2 h = __floats2half2_rn(r.x, r.y);
            u[j] = *reinterpret_cast<unsigned int*>(&h);
        }
        dst[i] = make_uint4(u[0],u[1],u[2],u[3]);
    }
}

// ------------- Stage B: iFFT along x (four-step 16x20) + coil combine; block = (my, t-half) ---
// dynamic smem: sIn[16*321] | sMid[16*340] | tw[320] | sS[320] = 89728 B
__global__ void __launch_bounds__(320, 2) stageB_kernel(){
    extern __shared__ float2 dyn[];
    float2* sIn  = dyn;                 // [f][x]  stride 321
    float2* sMid = sIn + 16*321;        // [f][m*17 + n1]  (n1: 0..15, pad to 17)
    float2* tw   = sMid + 16*340;       // 320
    float2* sS   = tw + 320;            // 320 (per-coil smaps row)
    const int my = blockIdx.x, half = blockIdx.y;
    const int tid = threadIdx.x;        // = x for gmem I/O
    tw[tid] = g_tw320[tid];
    const int f1 = tid >> 4, n1 = tid & 15;      // phase-1 ids (tid < 256)
    const int f2 = tid / 20, m2 = tid % 20;      // phase-2 ids

    float2 acc[16];
    #pragma unroll
    for (int i = 0; i < 16; i++) acc[i] = make_float2(0.f,0.f);

    uint4 pf[4];
    {
        const uint4* s0 = g_tmpH + ((size_t)(tid*20 + 0)*320 + my)*8 + half*4;
        #pragma unroll
        for (int i = 0; i < 4; i++) pf[i] = s0[i];
    }

    for (int c = 0; c < 20; c++){
        __syncthreads();                 // prev phase1 done with sIn, prev phase2 done with sMid/sS
        #pragma unroll
        for (int i = 0; i < 4; i++){
            unsigned int w0 = pf[i].x, w1 = pf[i].y, w2 = pf[i].z, w3 = pf[i].w;
            sIn[(4*i+0)*321 + tid] = __half22float2(*reinterpret_cast<__half2*>(&w0));
            sIn[(4*i+1)*321 + tid] = __half22float2(*reinterpret_cast<__half2*>(&w1));
            sIn[(4*i+2)*321 + tid] = __half22float2(*reinterpret_cast<__half2*>(&w2));
            sIn[(4*i+3)*321 + tid] = __half22float2(*reinterpret_cast<__half2*>(&w3));
        }
        sS[tid] = g_sT[(my*20 + c)*320 + tid];
        __syncthreads();

        // phase 1: (f, n1) — 256 tasks; 20-pt DFT over n2 (stride 16)
        if (tid < 256){
            const float2* base = sIn + f1*321;
            float2 v[20];
            #pragma unroll
            for (int n2 = 0; n2 < 20; n2++) v[n2] = base[n1 + 16*n2];
            dft20_reg(v);
            float2* mb = sMid + f1*340 + n1;
            int idx = 0;                              // n1*m mod 320
            #pragma unroll
            for (int m = 0; m < 20; m++){
                mb[m*17] = cmul(v[m], tw[idx]);
                idx += n1; if (idx >= 320) idx -= 320;
            }
        }
        // prefetch next coil (latency covered by phase 2)
        if (c < 19){
            const uint4* sn = g_tmpH + ((size_t)(tid*20 + c+1)*320 + my)*8 + half*4;
            #pragma unroll
            for (int i = 0; i < 4; i++) pf[i] = sn[i];
        }
        __syncthreads();

        // phase 2: (f, m) — 320 tasks; 16-pt FFT over n1; out[p] = X[m+20p]; accumulate
        {
            const float2* mb = sMid + f2*340 + m2*17;
            float2 v[16];
            #pragma unroll
            for (int k = 0; k < 16; k++) v[k] = mb[k];
            fft16_reg(v);
            #pragma unroll
            for (int p = 0; p < 16; p++)
                acc[p] = cadd(acc[p], cmul(v[p], sS[m2 + 20*p]));
        }
    }

    __syncthreads();
    {   // transpose acc through sIn for coalesced g_imt stores
        float2* ob = sIn + f2*321 + m2;
        #pragma unroll
        for (int p = 0; p < 16; p++) ob[20*p] = acc[p];   // x = m2 + 20p
    }
    __syncthreads();
    const int nv = half ? 9 : 16;
    const float sc = ((tid + my) & 1) ? -(1.f/320.f) : (1.f/320.f);  // post-shift + ortho norm
    for (int f = 0; f < nv; f++){
        int t = half*16 + f;
        float2 r = sIn[f*321 + tid];
        g_imt[((size_t)t*320 + my)*320 + tid] = make_float2(r.x*sc, r.y*sc);
    }
}

// ------------- Stage C: 25-frame bilinear warp + sum ------------------------------------------
__global__ void __launch_bounds__(256) stageC_kernel(
    const float* __restrict__ flow, float* __restrict__ out){
    int p = blockIdx.x*256 + threadIdx.x;             // 0..102399
    int x = p % 320;                                  // x fastest -> coalesced gathers
    int y = p / 320;
    const float* fl = flow + (x*320 + y)*50;          // [x][y][2][25]
    float2 acc = make_float2(0.f, 0.f);
    for (int t = 0; t < 25; t++){
        float u = fl[t], v = fl[25 + t];
        float xs = fminf(fmaxf((float)x + u, 0.f), 319.f);
        float ys = fminf(fmaxf((float)y + v, 0.f), 319.f);
        int x0 = (int)floorf(xs), y0 = (int)floorf(ys);
        int x1 = min(x0 + 1, 319), y1 = min(y0 + 1, 319);
        float wx = xs - (float)x0, wy = ys - (float)y0;
        const float2* im = g_imt + (size_t)t*102400;  // [y][x]
        float2 v00 = im[y0*320 + x0];
        float2 v10 = im[y0*320 + x1];
        float2 v01 = im[y1*320 + x0];
        float2 v11 = im[y1*320 + x1];
        float w00 = (1.f-wx)*(1.f-wy), w10 = wx*(1.f-wy);
        float w01 = (1.f-wx)*wy,       w11 = wx*wy;
        acc.x += v00.x*w00 + v10.x*w10 + v01.x*w01 + v11.x*w11;
        acc.y += v00.y*w00 + v10.y*w10 + v01.y*w01 + v11.y*w11;
    }
    out[x*320 + y]          = acc.x;                  // [2,Nx,Ny]: real plane
    out[102400 + x*320 + y] = acc.y;                  // imag plane
}

extern "C" void kernel_launch(void* const* d_in, const int* in_sizes, int n_in,
                              void* d_out, int out_size) {
    const float* kre  = (const float*)d_in[0];
    const float* kim  = (const float*)d_in[1];
    const float* mask = (const float*)d_in[2];
    const float* sre  = (const float*)d_in[3];
    const float* sim  = (const float*)d_in[4];
    const float* flow = (const float*)d_in[5];
    float* out = (float*)d_out;

    const int smemA = (16*321 + 16*336 + 320) * (int)sizeof(float2);        // 86656
    const int smemB = (16*321 + 16*340 + 320 + 320) * (int)sizeof(float2);  // 89728
    cudaFuncSetAttribute(stageA_kernel, cudaFuncAttributeMaxDynamicSharedMemorySize, smemA);
    cudaFuncSetAttribute(stageB_kernel, cudaFuncAttributeMaxDynamicSharedMemorySize, smemB);

    twinit_kernel<<<1, 320>>>();
    prep_kernel<<<400, 256>>>(kre, kim, sre, sim);
    stageA_kernel<<<dim3(320, 20, 2), 320, smemA>>>(mask);
    stageB_kernel<<<dim3(320, 2), 320, smemB>>>();
    stageC_kernel<<<400, 256>>>(flow, out);
}